// round 8
// baseline (speedup 1.0000x reference)
#include <cuda_runtime.h>
#include <cuda_fp16.h>
#include <cstdint>

#define B_  8
#define S_  512
#define D_  1024
#define V_  32000
#define ND_ 8

#define BM 256
#define BN 128
#define BK 32
#define NCHUNK (D_ / BK)        // 32
#define NT 512                  // threads per CTA (16 warps)

#define ROWB 80                 // smem bytes per row: 64 data + 16 pad (conflict-free)
#define A_STAGE_B (BM * ROWB)   // 20480
#define B_STAGE_B (BN * ROWB)   // 10240
#define OFF_A0 0
#define OFF_A1 A_STAGE_B
#define OFF_B0 (2 * A_STAGE_B)
#define OFF_B1 (2 * A_STAGE_B + B_STAGE_B)
#define SMEM_TOTAL (2 * A_STAGE_B + 2 * B_STAGE_B)   // 61440

__device__ __half g_hidden[B_ * S_ * D_];   // fp16 base-proj output
__device__ __half g_hs_h[B_ * S_ * D_];     // fp16 hidden_states

// ---------------- helpers ----------------
__device__ __forceinline__ uint32_t smem_u32(const void* p) {
    uint32_t a;
    asm("{ .reg .u64 t; cvta.to.shared.u64 t, %1; cvt.u32.u64 %0, t; }" : "=r"(a) : "l"(p));
    return a;
}
__device__ __forceinline__ uint32_t pack_h2(float x, float y) {
    uint32_t d;
    asm("cvt.rn.f16x2.f32 %0, %2, %1;" : "=r"(d) : "f"(x), "f"(y));
    return d;
}
__device__ __forceinline__ void cp16(uint32_t d, const void* s) {
    asm volatile("cp.async.cg.shared.global [%0], [%1], 16;" :: "r"(d), "l"(s));
}
__device__ __forceinline__ void ldsm_x4(uint32_t* r, uint32_t addr) {
    asm volatile("ldmatrix.sync.aligned.m8n8.x4.shared.b16 {%0,%1,%2,%3}, [%4];"
                 : "=r"(r[0]), "=r"(r[1]), "=r"(r[2]), "=r"(r[3]) : "r"(addr));
}
__device__ __forceinline__ void mma_f16(float* d, const uint32_t* a, const uint32_t* b) {
    asm volatile(
        "mma.sync.aligned.m16n8k16.row.col.f32.f16.f16.f32 "
        "{%0,%1,%2,%3}, {%4,%5,%6,%7}, {%8,%9}, {%0,%1,%2,%3};"
        : "+f"(d[0]), "+f"(d[1]), "+f"(d[2]), "+f"(d[3])
        : "r"(a[0]), "r"(a[1]), "r"(a[2]), "r"(a[3]), "r"(b[0]), "r"(b[1]));
}

// ---------------------------------------------------------------------------
// C[m0:m0+256, n0:n0+128] = A[m0:, :1024] @ B[:1024, n0:] + bias
// 512 threads, 16 warps (8m x 2n), warp tile 32x64.
// ---------------------------------------------------------------------------
template <bool HIDDEN_OUT>
__device__ __forceinline__ void gemm_tile(
    const __half* __restrict__ A,
    const float*  __restrict__ Bsrc,
    const float*  __restrict__ bias,
    float* __restrict__ C, __half* __restrict__ Chalf,
    int Nld, int m0, int n0)
{
    extern __shared__ char smem[];
    const uint32_t sb = smem_u32(smem);

    const int t    = threadIdx.x;
    const int lane = t & 31;
    const int wid  = t >> 5;
    const int wm   = wid >> 1;       // 0..7 : 32 rows each
    const int wn   = wid & 1;        // 0..1 : 64 cols each

    // B transpose mapping: thread owns column n=bn, k-rows [bk0, bk0+8)
    const int bn  = t & 127;
    const int bk0 = (t >> 7) * 8;    // 0,8,16,24

    const int aRowOff = (wm * 32 + (lane & 15)) * ROWB + (lane >> 4) * 16;
    const int bRowOff = (wn * 64 + (lane & 7) + ((lane >> 4) ? 8 : 0)) * ROWB
                      + ((lane >> 3) & 1) * 16;

    float acc[2][8][4];
    #pragma unroll
    for (int mt = 0; mt < 2; mt++)
        #pragma unroll
        for (int nt = 0; nt < 8; nt++)
            #pragma unroll
            for (int r = 0; r < 4; r++) acc[mt][nt][r] = 0.0f;

    float vpre[8];

    // ---- prologue: stage chunk 0 ----
    {
        #pragma unroll
        for (int i = 0; i < 2; i++) {
            const int idx = i * NT + t;
            const int row = idx >> 2, q = idx & 3;
            cp16(sb + OFF_A0 + row * ROWB + q * 16,
                 A + (size_t)(m0 + row) * D_ + q * 8);
        }
        asm volatile("cp.async.commit_group;" ::: "memory");

        const float* p = Bsrc + (size_t)bk0 * Nld + n0 + bn;
        #pragma unroll
        for (int kk = 0; kk < 8; kk++) vpre[kk] = p[(size_t)kk * Nld];

        uint32_t hw[4];
        #pragma unroll
        for (int j = 0; j < 4; j++) hw[j] = pack_h2(vpre[2*j], vpre[2*j+1]);
        const uint32_t dst = sb + OFF_B0 + bn * ROWB + bk0 * 2;
        asm volatile("st.shared.v4.b32 [%0], {%1,%2,%3,%4};" :: "r"(dst),
            "r"(hw[0]), "r"(hw[1]), "r"(hw[2]), "r"(hw[3]) : "memory");

        asm volatile("cp.async.wait_group 0;" ::: "memory");
        __syncthreads();
    }

    // ---- mainloop ----
    for (int c = 0; c < NCHUNK; c++) {
        const int buf = c & 1;
        const bool has_next = (c + 1 < NCHUNK);
        const uint32_t aBase  = sb + (buf ? OFF_A1 : OFF_A0);
        const uint32_t bBase  = sb + (buf ? OFF_B1 : OFF_B0);
        const uint32_t aBaseN = sb + (buf ? OFF_A0 : OFF_A1);
        const uint32_t bBaseN = sb + (buf ? OFF_B0 : OFF_B1);

        if (has_next) {
            const int k0n = (c + 1) * BK;
            #pragma unroll
            for (int i = 0; i < 2; i++) {
                const int idx = i * NT + t;
                const int row = idx >> 2, q = idx & 3;
                cp16(aBaseN + row * ROWB + q * 16,
                     A + (size_t)(m0 + row) * D_ + k0n + q * 8);
            }
            asm volatile("cp.async.commit_group;" ::: "memory");
            const float* p = Bsrc + (size_t)(k0n + bk0) * Nld + n0 + bn;
            #pragma unroll
            for (int kk = 0; kk < 8; kk++) vpre[kk] = p[(size_t)kk * Nld];
        }

        #pragma unroll
        for (int ks = 0; ks < 2; ks++) {
            uint32_t afr[2][4], bfr[4][4];
            #pragma unroll
            for (int mt = 0; mt < 2; mt++)
                ldsm_x4(afr[mt], aBase + aRowOff + mt * 16 * ROWB + ks * 32);
            #pragma unroll
            for (int p4 = 0; p4 < 4; p4++)
                ldsm_x4(bfr[p4], bBase + bRowOff + p4 * 16 * ROWB + ks * 32);
            #pragma unroll
            for (int mt = 0; mt < 2; mt++)
                #pragma unroll
                for (int p4 = 0; p4 < 4; p4++) {
                    mma_f16(acc[mt][2*p4+0], afr[mt], &bfr[p4][0]);
                    mma_f16(acc[mt][2*p4+1], afr[mt], &bfr[p4][2]);
                }
        }

        if (has_next) {
            uint32_t hw[4];
            #pragma unroll
            for (int j = 0; j < 4; j++) hw[j] = pack_h2(vpre[2*j], vpre[2*j+1]);
            const uint32_t dst = bBaseN + bn * ROWB + bk0 * 2;
            asm volatile("st.shared.v4.b32 [%0], {%1,%2,%3,%4};" :: "r"(dst),
                "r"(hw[0]), "r"(hw[1]), "r"(hw[2]), "r"(hw[3]) : "memory");
            asm volatile("cp.async.wait_group 0;" ::: "memory");
        }
        __syncthreads();
    }

    // ---- epilogue ----
    const int gid = lane >> 2, tig = lane & 3;
    #pragma unroll
    for (int mt = 0; mt < 2; mt++) {
        const int r0 = m0 + wm * 32 + mt * 16 + gid;
        #pragma unroll
        for (int nt = 0; nt < 8; nt++) {
            const int col = n0 + wn * 64 + nt * 8 + tig * 2;
            const float2 bv = *reinterpret_cast<const float2*>(bias + col);
            const float o0x = acc[mt][nt][0] + bv.x, o0y = acc[mt][nt][1] + bv.y;
            const float o1x = acc[mt][nt][2] + bv.x, o1y = acc[mt][nt][3] + bv.y;
            if (HIDDEN_OUT) {
                *reinterpret_cast<uint32_t*>(Chalf + (size_t)r0 * Nld + col)       = pack_h2(o0x, o0y);
                *reinterpret_cast<uint32_t*>(Chalf + (size_t)(r0 + 8) * Nld + col) = pack_h2(o1x, o1y);
            } else {
                *reinterpret_cast<float2*>(C + (size_t)r0 * Nld + col)       = make_float2(o0x, o0y);
                *reinterpret_cast<float2*>(C + (size_t)(r0 + 8) * Nld + col) = make_float2(o1x, o1y);
            }
        }
    }
}

// ---------------- kernels ----------------
__global__ __launch_bounds__(256) void round_hs_kernel(const float* __restrict__ hs) {
    const int i = (blockIdx.x * 256 + threadIdx.x) * 4;
    float4 v = *reinterpret_cast<const float4*>(hs + i);
    uint2 o;
    o.x = pack_h2(v.x, v.y);
    o.y = pack_h2(v.z, v.w);
    *reinterpret_cast<uint2*>(g_hs_h + i) = o;
}

__global__ __launch_bounds__(NT, 2) void gemm_base_kernel(
    const float* __restrict__ Wb, const float* __restrict__ bb)
{
    gemm_tile<true>(g_hs_h, Wb, bb, nullptr, g_hidden, D_,
                    blockIdx.y * BM, blockIdx.x * BN);
}

__global__ __launch_bounds__(NT, 2) void gemm_heads_kernel(
    const int* __restrict__ dom, const float* __restrict__ Wh,
    const float* __restrict__ bh, float* __restrict__ out)
{
    const int b = blockIdx.z;
    const int id = dom[b];
    const int idx = (id >= 0 && id < ND_) ? id : ND_;
    gemm_tile<false>(g_hidden + (size_t)b * S_ * D_,
                     Wh + (size_t)idx * D_ * V_,
                     bh + (size_t)idx * V_,
                     out + (size_t)b * S_ * V_, nullptr,
                     V_, blockIdx.y * BM, blockIdx.x * BN);
}

// ---------------- launch ----------------
extern "C" void kernel_launch(void* const* d_in, const int* in_sizes, int n_in,
                              void* d_out, int out_size)
{
    const float* hs      = (const float*)d_in[0];
    const int*   dom     = (const int*)  d_in[1];
    const float* W_base  = (const float*)d_in[2];
    const float* b_base  = (const float*)d_in[3];
    const float* W_heads = (const float*)d_in[4];
    const float* b_heads = (const float*)d_in[5];
    float* out = (float*)d_out;

    static bool attr_set = false;
    if (!attr_set) {
        cudaFuncSetAttribute(gemm_base_kernel,  cudaFuncAttributeMaxDynamicSharedMemorySize, SMEM_TOTAL);
        cudaFuncSetAttribute(gemm_heads_kernel, cudaFuncAttributeMaxDynamicSharedMemorySize, SMEM_TOTAL);
        attr_set = true;
    }

    round_hs_kernel<<<(B_ * S_ * D_) / (256 * 4), 256>>>(hs);

    dim3 gA(D_ / BN, (B_ * S_) / BM, 1);          // (8, 16, 1)
    gemm_base_kernel<<<gA, NT, SMEM_TOTAL>>>(W_base, b_base);

    dim3 gB(V_ / BN, S_ / BM, B_);                // (250, 2, 8)
    gemm_heads_kernel<<<gB, NT, SMEM_TOTAL>>>(dom, W_heads, b_heads, out);
}

// round 9
// speedup vs baseline: 2.7899x; 2.7899x over previous
#include <cuda_runtime.h>
#include <cuda_fp16.h>
#include <cstdint>

#define B_  8
#define S_  512
#define D_  1024
#define V_  32000
#define ND_ 8

#define BM 256
#define BN 128
#define BK 32
#define NCHUNK (D_ / BK)        // 32

// A smem: 80B rows (64 data + 16 pad)
#define ROWB 80
#define A_STAGE_B (BM * ROWB)               // 20480
// base-kernel B smem (fp16 [n][k] transposed path): 80B rows
#define BF_STAGE_B (BN * ROWB)              // 10240
// heads-kernel B smem (fp16 [k][n] direct path): 272B rows (256 data + 16 pad)
#define HBROW 272
#define HB_STAGE_B (BK * HBROW)             // 8704

#define OFF_A0 0
#define OFF_A1 A_STAGE_B
#define OFF_B0 (2 * A_STAGE_B)
// base:  B0/B1 at OFF_B0 / OFF_B0+BF_STAGE_B  -> total 61440
// heads: B0/B1 at OFF_B0 / OFF_B0+HB_STAGE_B  -> total 58368
#define SMEM_BASE_TOTAL  (2 * A_STAGE_B + 2 * BF_STAGE_B)
#define SMEM_HEADS_TOTAL (2 * A_STAGE_B + 2 * HB_STAGE_B)

__device__ __half g_hidden[B_ * S_ * D_];        // fp16 base-proj output
__device__ __half g_hs_h[B_ * S_ * D_];          // fp16 hidden_states
__device__ __half g_whB[(size_t)B_ * D_ * V_];   // fp16 gathered head weights (per batch, dedup by owner)

// ---------------- helpers ----------------
__device__ __forceinline__ uint32_t smem_u32(const void* p) {
    uint32_t a;
    asm("{ .reg .u64 t; cvta.to.shared.u64 t, %1; cvt.u32.u64 %0, t; }" : "=r"(a) : "l"(p));
    return a;
}
__device__ __forceinline__ uint32_t pack_h2(float x, float y) {
    uint32_t d;
    asm("cvt.rn.f16x2.f32 %0, %2, %1;" : "=r"(d) : "f"(x), "f"(y));
    return d;
}
__device__ __forceinline__ void cp16(uint32_t d, const void* s) {
    asm volatile("cp.async.cg.shared.global [%0], [%1], 16;" :: "r"(d), "l"(s));
}
__device__ __forceinline__ void ldsm_x4(uint32_t* r, uint32_t addr) {
    asm volatile("ldmatrix.sync.aligned.m8n8.x4.shared.b16 {%0,%1,%2,%3}, [%4];"
                 : "=r"(r[0]), "=r"(r[1]), "=r"(r[2]), "=r"(r[3]) : "r"(addr));
}
__device__ __forceinline__ void ldsm_x4_t(uint32_t* r, uint32_t addr) {
    asm volatile("ldmatrix.sync.aligned.m8n8.x4.trans.shared.b16 {%0,%1,%2,%3}, [%4];"
                 : "=r"(r[0]), "=r"(r[1]), "=r"(r[2]), "=r"(r[3]) : "r"(addr));
}
__device__ __forceinline__ void mma_f16(float* d, const uint32_t* a, const uint32_t* b) {
    asm volatile(
        "mma.sync.aligned.m16n8k16.row.col.f32.f16.f16.f32 "
        "{%0,%1,%2,%3}, {%4,%5,%6,%7}, {%8,%9}, {%0,%1,%2,%3};"
        : "+f"(d[0]), "+f"(d[1]), "+f"(d[2]), "+f"(d[3])
        : "r"(a[0]), "r"(a[1]), "r"(a[2]), "r"(a[3]), "r"(b[0]), "r"(b[1]));
}
__device__ __forceinline__ int clamp_idx(int id) {
    return (id >= 0 && id < ND_) ? id : ND_;
}

// ===========================================================================
// BASE kernel: R6-proven fp32-B transpose path (unchanged numerics).
// 256 threads, 8 warps (4m x 2n), warp tile 64x64. Writes fp16 g_hidden.
// ===========================================================================
__global__ __launch_bounds__(256, 1) void gemm_base_kernel(
    const float* __restrict__ Wb, const float* __restrict__ bb)
{
    extern __shared__ char smem[];
    const uint32_t sb = smem_u32(smem);
    const __half* A = g_hs_h;
    const int Nld = D_;
    const int m0 = blockIdx.y * BM, n0 = blockIdx.x * BN;

    const int t    = threadIdx.x;
    const int lane = t & 31;
    const int wid  = t >> 5;
    const int wm   = wid >> 1;
    const int wn   = wid & 1;
    const int bn   = t & 127;
    const int bk0  = (t >> 7) * 16;

    const int aRowOff = (wm * 64 + (lane & 15)) * ROWB + (lane >> 4) * 16;
    const int bRowOff = (wn * 64 + (lane & 7) + ((lane >> 4) ? 8 : 0)) * ROWB
                      + ((lane >> 3) & 1) * 16;

    float acc[4][8][4];
    #pragma unroll
    for (int mt = 0; mt < 4; mt++)
        #pragma unroll
        for (int nt = 0; nt < 8; nt++)
            #pragma unroll
            for (int r = 0; r < 4; r++) acc[mt][nt][r] = 0.0f;

    float vpre[16];
    {
        #pragma unroll
        for (int i = 0; i < 4; i++) {
            const int idx = i * 256 + t;
            const int row = idx >> 2, q = idx & 3;
            cp16(sb + OFF_A0 + row * ROWB + q * 16,
                 A + (size_t)(m0 + row) * D_ + q * 8);
        }
        asm volatile("cp.async.commit_group;" ::: "memory");

        const float* p = Wb + (size_t)bk0 * Nld + n0 + bn;
        #pragma unroll
        for (int kk = 0; kk < 16; kk++) vpre[kk] = p[(size_t)kk * Nld];

        uint32_t hw[8];
        #pragma unroll
        for (int j = 0; j < 8; j++) hw[j] = pack_h2(vpre[2*j], vpre[2*j+1]);
        const uint32_t dst = sb + OFF_B0 + bn * ROWB + bk0 * 2;
        asm volatile("st.shared.v4.b32 [%0], {%1,%2,%3,%4};" :: "r"(dst),
            "r"(hw[0]), "r"(hw[1]), "r"(hw[2]), "r"(hw[3]) : "memory");
        asm volatile("st.shared.v4.b32 [%0], {%1,%2,%3,%4};" :: "r"(dst + 16),
            "r"(hw[4]), "r"(hw[5]), "r"(hw[6]), "r"(hw[7]) : "memory");

        asm volatile("cp.async.wait_group 0;" ::: "memory");
        __syncthreads();
    }

    for (int c = 0; c < NCHUNK; c++) {
        const int buf = c & 1;
        const bool has_next = (c + 1 < NCHUNK);
        const uint32_t aBase  = sb + (buf ? OFF_A1 : OFF_A0);
        const uint32_t bBase  = sb + OFF_B0 + (buf ? BF_STAGE_B : 0);
        const uint32_t aBaseN = sb + (buf ? OFF_A0 : OFF_A1);
        const uint32_t bBaseN = sb + OFF_B0 + (buf ? 0 : BF_STAGE_B);

        if (has_next) {
            const int k0n = (c + 1) * BK;
            #pragma unroll
            for (int i = 0; i < 4; i++) {
                const int idx = i * 256 + t;
                const int row = idx >> 2, q = idx & 3;
                cp16(aBaseN + row * ROWB + q * 16,
                     A + (size_t)(m0 + row) * D_ + k0n + q * 8);
            }
            asm volatile("cp.async.commit_group;" ::: "memory");
            const float* p = Wb + (size_t)(k0n + bk0) * Nld + n0 + bn;
            #pragma unroll
            for (int kk = 0; kk < 16; kk++) vpre[kk] = p[(size_t)kk * Nld];
        }

        #pragma unroll
        for (int ks = 0; ks < 2; ks++) {
            uint32_t afr[4][4], bfr[4][4];
            #pragma unroll
            for (int mt = 0; mt < 4; mt++)
                ldsm_x4(afr[mt], aBase + aRowOff + mt * 16 * ROWB + ks * 32);
            #pragma unroll
            for (int p4 = 0; p4 < 4; p4++)
                ldsm_x4(bfr[p4], bBase + bRowOff + p4 * 16 * ROWB + ks * 32);
            #pragma unroll
            for (int mt = 0; mt < 4; mt++)
                #pragma unroll
                for (int p4 = 0; p4 < 4; p4++) {
                    mma_f16(acc[mt][2*p4+0], afr[mt], &bfr[p4][0]);
                    mma_f16(acc[mt][2*p4+1], afr[mt], &bfr[p4][2]);
                }
        }

        if (has_next) {
            uint32_t hw[8];
            #pragma unroll
            for (int j = 0; j < 8; j++) hw[j] = pack_h2(vpre[2*j], vpre[2*j+1]);
            const uint32_t dst = bBaseN + bn * ROWB + bk0 * 2;
            asm volatile("st.shared.v4.b32 [%0], {%1,%2,%3,%4};" :: "r"(dst),
                "r"(hw[0]), "r"(hw[1]), "r"(hw[2]), "r"(hw[3]) : "memory");
            asm volatile("st.shared.v4.b32 [%0], {%1,%2,%3,%4};" :: "r"(dst + 16),
                "r"(hw[4]), "r"(hw[5]), "r"(hw[6]), "r"(hw[7]) : "memory");
            asm volatile("cp.async.wait_group 0;" ::: "memory");
        }
        __syncthreads();
    }

    const int gid = lane >> 2, tig = lane & 3;
    #pragma unroll
    for (int mt = 0; mt < 4; mt++) {
        const int r0 = m0 + wm * 64 + mt * 16 + gid;
        #pragma unroll
        for (int nt = 0; nt < 8; nt++) {
            const int col = n0 + wn * 64 + nt * 8 + tig * 2;
            const float2 bv = *reinterpret_cast<const float2*>(bb + col);
            *reinterpret_cast<uint32_t*>(g_hidden + (size_t)r0 * Nld + col) =
                pack_h2(acc[mt][nt][0] + bv.x, acc[mt][nt][1] + bv.y);
            *reinterpret_cast<uint32_t*>(g_hidden + (size_t)(r0 + 8) * Nld + col) =
                pack_h2(acc[mt][nt][2] + bv.x, acc[mt][nt][3] + bv.y);
        }
    }
}

// ===========================================================================
// HEADS kernel: fp16 B via cp.async [k][n] + ldmatrix.trans (no in-loop cvt).
// ===========================================================================
__global__ __launch_bounds__(256, 1) void gemm_heads_kernel(
    const int* __restrict__ dom, const float* __restrict__ bh,
    float* __restrict__ out)
{
    extern __shared__ char smem[];
    const uint32_t sb = smem_u32(smem);

    const int b = blockIdx.z;
    const int idx = clamp_idx(dom[b]);
    int ob = b;                                  // owner batch holding this head in g_whB
    for (int bb = 0; bb < b; bb++)
        if (clamp_idx(dom[bb]) == idx) { ob = bb; break; }

    const __half* A   = g_hidden + (size_t)b * S_ * D_;
    const __half* Bh  = g_whB + (size_t)ob * D_ * V_;
    const float* bias = bh + (size_t)idx * V_;
    float* C          = out + (size_t)b * S_ * V_;
    const int Nld = V_;
    const int m0 = blockIdx.y * BM, n0 = blockIdx.x * BN;

    const int t    = threadIdx.x;
    const int lane = t & 31;
    const int wid  = t >> 5;
    const int wm   = wid >> 1;
    const int wn   = wid & 1;

    const int aRowOff = (wm * 64 + (lane & 15)) * ROWB + (lane >> 4) * 16;
    // trans-B lane offset: rows k (lanes 0-15 -> k0..15), lanes 16-31 -> n+8
    const int bLaneOff = ((lane & 7) + ((lane >> 3) & 1) * 8) * HBROW + (lane >> 4) * 16;

    float acc[4][8][4];
    #pragma unroll
    for (int mt = 0; mt < 4; mt++)
        #pragma unroll
        for (int nt = 0; nt < 8; nt++)
            #pragma unroll
            for (int r = 0; r < 4; r++) acc[mt][nt][r] = 0.0f;

    // prologue: stage chunk 0 (A: 4 cp16/thread, B: 2 cp16/thread)
    {
        #pragma unroll
        for (int i = 0; i < 4; i++) {
            const int idq = i * 256 + t;
            const int row = idq >> 2, q = idq & 3;
            cp16(sb + OFF_A0 + row * ROWB + q * 16,
                 A + (size_t)(m0 + row) * D_ + q * 8);
        }
        #pragma unroll
        for (int i = 0; i < 2; i++) {
            const int idq = i * 256 + t;
            const int row = idq >> 4, seg = idq & 15;
            cp16(sb + OFF_B0 + row * HBROW + seg * 16,
                 Bh + (size_t)row * Nld + n0 + seg * 8);
        }
        asm volatile("cp.async.commit_group;" ::: "memory");
        asm volatile("cp.async.wait_group 0;" ::: "memory");
        __syncthreads();
    }

    for (int c = 0; c < NCHUNK; c++) {
        const int buf = c & 1;
        const bool has_next = (c + 1 < NCHUNK);
        const uint32_t aBase  = sb + (buf ? OFF_A1 : OFF_A0);
        const uint32_t bBase  = sb + OFF_B0 + (buf ? HB_STAGE_B : 0);
        const uint32_t aBaseN = sb + (buf ? OFF_A0 : OFF_A1);
        const uint32_t bBaseN = sb + OFF_B0 + (buf ? 0 : HB_STAGE_B);

        if (has_next) {
            const int k0n = (c + 1) * BK;
            #pragma unroll
            for (int i = 0; i < 4; i++) {
                const int idq = i * 256 + t;
                const int row = idq >> 2, q = idq & 3;
                cp16(aBaseN + row * ROWB + q * 16,
                     A + (size_t)(m0 + row) * D_ + k0n + q * 8);
            }
            #pragma unroll
            for (int i = 0; i < 2; i++) {
                const int idq = i * 256 + t;
                const int row = idq >> 4, seg = idq & 15;
                cp16(bBaseN + row * HBROW + seg * 16,
                     Bh + (size_t)(k0n + row) * Nld + n0 + seg * 8);
            }
            asm volatile("cp.async.commit_group;" ::: "memory");
        }

        #pragma unroll
        for (int ks = 0; ks < 2; ks++) {
            uint32_t afr[4][4], bfr[4][4];
            #pragma unroll
            for (int mt = 0; mt < 4; mt++)
                ldsm_x4(afr[mt], aBase + aRowOff + mt * 16 * ROWB + ks * 32);
            #pragma unroll
            for (int p4 = 0; p4 < 4; p4++)
                ldsm_x4_t(bfr[p4], bBase + bLaneOff + ks * 16 * HBROW
                                 + (wn * 64 + p4 * 16) * 2);
            #pragma unroll
            for (int mt = 0; mt < 4; mt++)
                #pragma unroll
                for (int p4 = 0; p4 < 4; p4++) {
                    mma_f16(acc[mt][2*p4+0], afr[mt], &bfr[p4][0]);
                    mma_f16(acc[mt][2*p4+1], afr[mt], &bfr[p4][2]);
                }
        }

        if (has_next) {
            asm volatile("cp.async.wait_group 0;" ::: "memory");
        }
        __syncthreads();
    }

    const int gid = lane >> 2, tig = lane & 3;
    #pragma unroll
    for (int mt = 0; mt < 4; mt++) {
        const int r0 = m0 + wm * 64 + mt * 16 + gid;
        #pragma unroll
        for (int nt = 0; nt < 8; nt++) {
            const int col = n0 + wn * 64 + nt * 8 + tig * 2;
            const float2 bv = *reinterpret_cast<const float2*>(bias + col);
            *reinterpret_cast<float2*>(C + (size_t)r0 * Nld + col) =
                make_float2(acc[mt][nt][0] + bv.x, acc[mt][nt][1] + bv.y);
            *reinterpret_cast<float2*>(C + (size_t)(r0 + 8) * Nld + col) =
                make_float2(acc[mt][nt][2] + bv.x, acc[mt][nt][3] + bv.y);
        }
    }
}

// ---------------- aux kernels ----------------
__global__ __launch_bounds__(256) void round_hs_kernel(const float* __restrict__ hs) {
    const int i = (blockIdx.x * 256 + threadIdx.x) * 4;
    float4 v = *reinterpret_cast<const float4*>(hs + i);
    uint2 o;
    o.x = pack_h2(v.x, v.y);
    o.y = pack_h2(v.z, v.w);
    *reinterpret_cast<uint2*>(g_hs_h + i) = o;
}

// Convert W_heads[idx[b]] fp32 -> g_whB[b] fp16 (skip duplicate heads: first owner only)
__global__ __launch_bounds__(256) void convert_w_kernel(
    const int* __restrict__ dom, const float* __restrict__ Wh)
{
    const int b = blockIdx.y;
    const int idx = clamp_idx(dom[b]);
    for (int bb = 0; bb < b; bb++)
        if (clamp_idx(dom[bb]) == idx) return;   // another batch already owns it

    const size_t i = ((size_t)blockIdx.x * 256 + threadIdx.x) * 8;
    const float* src = Wh + (size_t)idx * D_ * V_ + i;
    __half* dst = g_whB + (size_t)b * D_ * V_ + i;
    float4 v0 = *reinterpret_cast<const float4*>(src);
    float4 v1 = *reinterpret_cast<const float4*>(src + 4);
    uint4 o;
    o.x = pack_h2(v0.x, v0.y);
    o.y = pack_h2(v0.z, v0.w);
    o.z = pack_h2(v1.x, v1.y);
    o.w = pack_h2(v1.z, v1.w);
    *reinterpret_cast<uint4*>(dst) = o;
}

// ---------------- launch ----------------
extern "C" void kernel_launch(void* const* d_in, const int* in_sizes, int n_in,
                              void* d_out, int out_size)
{
    const float* hs      = (const float*)d_in[0];
    const int*   dom     = (const int*)  d_in[1];
    const float* W_base  = (const float*)d_in[2];
    const float* b_base  = (const float*)d_in[3];
    const float* W_heads = (const float*)d_in[4];
    const float* b_heads = (const float*)d_in[5];
    float* out = (float*)d_out;

    static bool attr_set = false;
    if (!attr_set) {
        cudaFuncSetAttribute(gemm_base_kernel,  cudaFuncAttributeMaxDynamicSharedMemorySize, SMEM_BASE_TOTAL);
        cudaFuncSetAttribute(gemm_heads_kernel, cudaFuncAttributeMaxDynamicSharedMemorySize, SMEM_HEADS_TOTAL);
        attr_set = true;
    }

    round_hs_kernel<<<(B_ * S_ * D_) / (256 * 4), 256>>>(hs);

    dim3 gC((D_ * V_) / (256 * 8), B_);           // (16000, 8)
    convert_w_kernel<<<gC, 256>>>(dom, W_heads);

    dim3 gA(D_ / BN, (B_ * S_) / BM, 1);          // (8, 16, 1)
    gemm_base_kernel<<<gA, 256, SMEM_BASE_TOTAL>>>(W_base, b_base);

    dim3 gB(V_ / BN, S_ / BM, B_);                // (250, 2, 8)
    gemm_heads_kernel<<<gB, 256, SMEM_HEADS_TOTAL>>>(dom, b_heads, out);
}

// round 10
// speedup vs baseline: 3.1990x; 1.1466x over previous
#include <cuda_runtime.h>
#include <cuda_fp16.h>
#include <cstdint>

#define B_  8
#define S_  512
#define D_  1024
#define V_  32000
#define ND_ 8

#define BM 256
#define BN 128

// ---- base kernel config (BK=32, R6-proven) ----
#define BKB 32
#define NCHUNKB (D_ / BKB)       // 32
#define ROWB 80                  // 64B data + 16 pad
#define AB_STAGE (BM * ROWB)     // 20480
#define BB_STAGE (BN * ROWB)     // 10240
#define SMEM_BASE_TOTAL (2 * AB_STAGE + 2 * BB_STAGE)    // 61440

// ---- heads kernel config (BK=64) ----
#define BKH 64
#define NCHUNKH (D_ / BKH)       // 16
#define HAROW 144                // 128B data + 16 pad (64 halves)
#define HBROW 272                // 256B data + 16 pad (128 halves)
#define HA_STAGE (BM * HAROW)    // 36864
#define HB_STAGE (BKH * HBROW)   // 17408
#define SMEM_HEADS_TOTAL (2 * HA_STAGE + 2 * HB_STAGE)   // 108544

__device__ __half g_hidden[B_ * S_ * D_];
__device__ __half g_hs_h[B_ * S_ * D_];
__device__ __half g_whB[(size_t)B_ * D_ * V_];

// ---------------- helpers ----------------
__device__ __forceinline__ uint32_t smem_u32(const void* p) {
    uint32_t a;
    asm("{ .reg .u64 t; cvta.to.shared.u64 t, %1; cvt.u32.u64 %0, t; }" : "=r"(a) : "l"(p));
    return a;
}
__device__ __forceinline__ uint32_t pack_h2(float x, float y) {
    uint32_t d;
    asm("cvt.rn.f16x2.f32 %0, %2, %1;" : "=r"(d) : "f"(x), "f"(y));
    return d;
}
__device__ __forceinline__ void cp16(uint32_t d, const void* s) {
    asm volatile("cp.async.cg.shared.global [%0], [%1], 16;" :: "r"(d), "l"(s));
}
__device__ __forceinline__ void ldsm_x4(uint32_t* r, uint32_t addr) {
    asm volatile("ldmatrix.sync.aligned.m8n8.x4.shared.b16 {%0,%1,%2,%3}, [%4];"
                 : "=r"(r[0]), "=r"(r[1]), "=r"(r[2]), "=r"(r[3]) : "r"(addr));
}
__device__ __forceinline__ void ldsm_x4_t(uint32_t* r, uint32_t addr) {
    asm volatile("ldmatrix.sync.aligned.m8n8.x4.trans.shared.b16 {%0,%1,%2,%3}, [%4];"
                 : "=r"(r[0]), "=r"(r[1]), "=r"(r[2]), "=r"(r[3]) : "r"(addr));
}
__device__ __forceinline__ void mma_f16(float* d, const uint32_t* a, const uint32_t* b) {
    asm volatile(
        "mma.sync.aligned.m16n8k16.row.col.f32.f16.f16.f32 "
        "{%0,%1,%2,%3}, {%4,%5,%6,%7}, {%8,%9}, {%0,%1,%2,%3};"
        : "+f"(d[0]), "+f"(d[1]), "+f"(d[2]), "+f"(d[3])
        : "r"(a[0]), "r"(a[1]), "r"(a[2]), "r"(a[3]), "r"(b[0]), "r"(b[1]));
}
__device__ __forceinline__ int clamp_idx(int id) {
    return (id >= 0 && id < ND_) ? id : ND_;
}

// ===========================================================================
// BASE kernel (unchanged from R9): fp32-B transpose path, BK=32.
// ===========================================================================
__global__ __launch_bounds__(256, 1) void gemm_base_kernel(
    const float* __restrict__ Wb, const float* __restrict__ bb)
{
    extern __shared__ char smem[];
    const uint32_t sb = smem_u32(smem);
    const __half* A = g_hs_h;
    const int Nld = D_;
    const int m0 = blockIdx.y * BM, n0 = blockIdx.x * BN;

    const int t    = threadIdx.x;
    const int lane = t & 31;
    const int wid  = t >> 5;
    const int wm   = wid >> 1;
    const int wn   = wid & 1;
    const int bn   = t & 127;
    const int bk0  = (t >> 7) * 16;

    const int aRowOff = (wm * 64 + (lane & 15)) * ROWB + (lane >> 4) * 16;
    const int bRowOff = (wn * 64 + (lane & 7) + ((lane >> 4) ? 8 : 0)) * ROWB
                      + ((lane >> 3) & 1) * 16;

    float acc[4][8][4];
    #pragma unroll
    for (int mt = 0; mt < 4; mt++)
        #pragma unroll
        for (int nt = 0; nt < 8; nt++)
            #pragma unroll
            for (int r = 0; r < 4; r++) acc[mt][nt][r] = 0.0f;

    float vpre[16];
    {
        #pragma unroll
        for (int i = 0; i < 4; i++) {
            const int idx = i * 256 + t;
            const int row = idx >> 2, q = idx & 3;
            cp16(sb + row * ROWB + q * 16, A + (size_t)(m0 + row) * D_ + q * 8);
        }
        asm volatile("cp.async.commit_group;" ::: "memory");

        const float* p = Wb + (size_t)bk0 * Nld + n0 + bn;
        #pragma unroll
        for (int kk = 0; kk < 16; kk++) vpre[kk] = p[(size_t)kk * Nld];

        uint32_t hw[8];
        #pragma unroll
        for (int j = 0; j < 8; j++) hw[j] = pack_h2(vpre[2*j], vpre[2*j+1]);
        const uint32_t dst = sb + 2 * AB_STAGE + bn * ROWB + bk0 * 2;
        asm volatile("st.shared.v4.b32 [%0], {%1,%2,%3,%4};" :: "r"(dst),
            "r"(hw[0]), "r"(hw[1]), "r"(hw[2]), "r"(hw[3]) : "memory");
        asm volatile("st.shared.v4.b32 [%0], {%1,%2,%3,%4};" :: "r"(dst + 16),
            "r"(hw[4]), "r"(hw[5]), "r"(hw[6]), "r"(hw[7]) : "memory");

        asm volatile("cp.async.wait_group 0;" ::: "memory");
        __syncthreads();
    }

    for (int c = 0; c < NCHUNKB; c++) {
        const int buf = c & 1;
        const bool has_next = (c + 1 < NCHUNKB);
        const uint32_t aBase  = sb + (buf ? AB_STAGE : 0);
        const uint32_t bBase  = sb + 2 * AB_STAGE + (buf ? BB_STAGE : 0);
        const uint32_t aBaseN = sb + (buf ? 0 : AB_STAGE);
        const uint32_t bBaseN = sb + 2 * AB_STAGE + (buf ? 0 : BB_STAGE);

        if (has_next) {
            const int k0n = (c + 1) * BKB;
            #pragma unroll
            for (int i = 0; i < 4; i++) {
                const int idx = i * 256 + t;
                const int row = idx >> 2, q = idx & 3;
                cp16(aBaseN + row * ROWB + q * 16,
                     A + (size_t)(m0 + row) * D_ + k0n + q * 8);
            }
            asm volatile("cp.async.commit_group;" ::: "memory");
            const float* p = Wb + (size_t)(k0n + bk0) * Nld + n0 + bn;
            #pragma unroll
            for (int kk = 0; kk < 16; kk++) vpre[kk] = p[(size_t)kk * Nld];
        }

        #pragma unroll
        for (int ks = 0; ks < 2; ks++) {
            uint32_t afr[4][4], bfr[4][4];
            #pragma unroll
            for (int mt = 0; mt < 4; mt++)
                ldsm_x4(afr[mt], aBase + aRowOff + mt * 16 * ROWB + ks * 32);
            #pragma unroll
            for (int p4 = 0; p4 < 4; p4++)
                ldsm_x4(bfr[p4], bBase + bRowOff + p4 * 16 * ROWB + ks * 32);
            #pragma unroll
            for (int mt = 0; mt < 4; mt++)
                #pragma unroll
                for (int p4 = 0; p4 < 4; p4++) {
                    mma_f16(acc[mt][2*p4+0], afr[mt], &bfr[p4][0]);
                    mma_f16(acc[mt][2*p4+1], afr[mt], &bfr[p4][2]);
                }
        }

        if (has_next) {
            uint32_t hw[8];
            #pragma unroll
            for (int j = 0; j < 8; j++) hw[j] = pack_h2(vpre[2*j], vpre[2*j+1]);
            const uint32_t dst = bBaseN + bn * ROWB + bk0 * 2;
            asm volatile("st.shared.v4.b32 [%0], {%1,%2,%3,%4};" :: "r"(dst),
                "r"(hw[0]), "r"(hw[1]), "r"(hw[2]), "r"(hw[3]) : "memory");
            asm volatile("st.shared.v4.b32 [%0], {%1,%2,%3,%4};" :: "r"(dst + 16),
                "r"(hw[4]), "r"(hw[5]), "r"(hw[6]), "r"(hw[7]) : "memory");
            asm volatile("cp.async.wait_group 0;" ::: "memory");
        }
        __syncthreads();
    }

    const int gid = lane >> 2, tig = lane & 3;
    #pragma unroll
    for (int mt = 0; mt < 4; mt++) {
        const int r0 = m0 + wm * 64 + mt * 16 + gid;
        #pragma unroll
        for (int nt = 0; nt < 8; nt++) {
            const int col = n0 + wn * 64 + nt * 8 + tig * 2;
            const float2 bv = *reinterpret_cast<const float2*>(bb + col);
            *reinterpret_cast<uint32_t*>(g_hidden + (size_t)r0 * Nld + col) =
                pack_h2(acc[mt][nt][0] + bv.x, acc[mt][nt][1] + bv.y);
            *reinterpret_cast<uint32_t*>(g_hidden + (size_t)(r0 + 8) * Nld + col) =
                pack_h2(acc[mt][nt][2] + bv.x, acc[mt][nt][3] + bv.y);
        }
    }
}

// ===========================================================================
// HEADS kernel: BK=64, fp16 B via cp.async + ldmatrix.trans.
// grid = (m:2, n:250, b:8)  -> m-twins adjacent for L2 sharing of B.
// ===========================================================================
__global__ __launch_bounds__(256, 1) void gemm_heads_kernel(
    const int* __restrict__ dom, const float* __restrict__ bh,
    float* __restrict__ out)
{
    extern __shared__ char smem[];
    const uint32_t sb = smem_u32(smem);

    const int b = blockIdx.z;
    const int idx = clamp_idx(dom[b]);
    int ob = b;
    for (int bb = 0; bb < b; bb++)
        if (clamp_idx(dom[bb]) == idx) { ob = bb; break; }

    const __half* A   = g_hidden + (size_t)b * S_ * D_;
    const __half* Bh  = g_whB + (size_t)ob * D_ * V_;
    const float* bias = bh + (size_t)idx * V_;
    float* C          = out + (size_t)b * S_ * V_;
    const int Nld = V_;
    const int m0 = blockIdx.x * BM, n0 = blockIdx.y * BN;

    const int t    = threadIdx.x;
    const int lane = t & 31;
    const int wid  = t >> 5;
    const int wm   = wid >> 1;
    const int wn   = wid & 1;

    const int aRowOff  = (wm * 64 + (lane & 15)) * HAROW + (lane >> 4) * 16;
    const int bLaneOff = ((lane & 7) + ((lane >> 3) & 1) * 8) * HBROW + (lane >> 4) * 16;

    float acc[4][8][4];
    #pragma unroll
    for (int mt = 0; mt < 4; mt++)
        #pragma unroll
        for (int nt = 0; nt < 8; nt++)
            #pragma unroll
            for (int r = 0; r < 4; r++) acc[mt][nt][r] = 0.0f;

    // prologue: stage chunk 0.  A: 256 rows x 8 segs = 2048 -> 8/thread.
    //                           B: 64 rows x 16 segs = 1024 -> 4/thread.
    {
        #pragma unroll
        for (int i = 0; i < 8; i++) {
            const int idq = i * 256 + t;
            const int row = idq >> 3, q = idq & 7;
            cp16(sb + row * HAROW + q * 16, A + (size_t)(m0 + row) * D_ + q * 8);
        }
        #pragma unroll
        for (int i = 0; i < 4; i++) {
            const int idq = i * 256 + t;
            const int row = idq >> 4, seg = idq & 15;
            cp16(sb + 2 * HA_STAGE + row * HBROW + seg * 16,
                 Bh + (size_t)row * Nld + n0 + seg * 8);
        }
        asm volatile("cp.async.commit_group;" ::: "memory");
        asm volatile("cp.async.wait_group 0;" ::: "memory");
        __syncthreads();
    }

    for (int c = 0; c < NCHUNKH; c++) {
        const int buf = c & 1;
        const bool has_next = (c + 1 < NCHUNKH);
        const uint32_t aBase  = sb + (buf ? HA_STAGE : 0);
        const uint32_t bBase  = sb + 2 * HA_STAGE + (buf ? HB_STAGE : 0);
        const uint32_t aBaseN = sb + (buf ? 0 : HA_STAGE);
        const uint32_t bBaseN = sb + 2 * HA_STAGE + (buf ? 0 : HB_STAGE);

        if (has_next) {
            const int k0n = (c + 1) * BKH;
            #pragma unroll
            for (int i = 0; i < 8; i++) {
                const int idq = i * 256 + t;
                const int row = idq >> 3, q = idq & 7;
                cp16(aBaseN + row * HAROW + q * 16,
                     A + (size_t)(m0 + row) * D_ + k0n + q * 8);
            }
            #pragma unroll
            for (int i = 0; i < 4; i++) {
                const int idq = i * 256 + t;
                const int row = idq >> 4, seg = idq & 15;
                cp16(bBaseN + row * HBROW + seg * 16,
                     Bh + (size_t)(k0n + row) * Nld + n0 + seg * 8);
            }
            asm volatile("cp.async.commit_group;" ::: "memory");
        }

        #pragma unroll
        for (int ks = 0; ks < 4; ks++) {
            uint32_t afr[4][4], bfr[4][4];
            #pragma unroll
            for (int mt = 0; mt < 4; mt++)
                ldsm_x4(afr[mt], aBase + aRowOff + mt * 16 * HAROW + ks * 32);
            #pragma unroll
            for (int p4 = 0; p4 < 4; p4++)
                ldsm_x4_t(bfr[p4], bBase + bLaneOff + ks * 16 * HBROW
                                 + (wn * 64 + p4 * 16) * 2);
            #pragma unroll
            for (int mt = 0; mt < 4; mt++)
                #pragma unroll
                for (int p4 = 0; p4 < 4; p4++) {
                    mma_f16(acc[mt][2*p4+0], afr[mt], &bfr[p4][0]);
                    mma_f16(acc[mt][2*p4+1], afr[mt], &bfr[p4][2]);
                }
        }

        if (has_next) {
            asm volatile("cp.async.wait_group 0;" ::: "memory");
        }
        __syncthreads();
    }

    const int gid = lane >> 2, tig = lane & 3;
    #pragma unroll
    for (int mt = 0; mt < 4; mt++) {
        const int r0 = m0 + wm * 64 + mt * 16 + gid;
        #pragma unroll
        for (int nt = 0; nt < 8; nt++) {
            const int col = n0 + wn * 64 + nt * 8 + tig * 2;
            const float2 bv = *reinterpret_cast<const float2*>(bias + col);
            *reinterpret_cast<float2*>(C + (size_t)r0 * Nld + col) =
                make_float2(acc[mt][nt][0] + bv.x, acc[mt][nt][1] + bv.y);
            *reinterpret_cast<float2*>(C + (size_t)(r0 + 8) * Nld + col) =
                make_float2(acc[mt][nt][2] + bv.x, acc[mt][nt][3] + bv.y);
        }
    }
}

// ---------------- aux kernels ----------------
__global__ __launch_bounds__(256) void round_hs_kernel(const float* __restrict__ hs) {
    const int i = (blockIdx.x * 256 + threadIdx.x) * 4;
    float4 v = *reinterpret_cast<const float4*>(hs + i);
    uint2 o;
    o.x = pack_h2(v.x, v.y);
    o.y = pack_h2(v.z, v.w);
    *reinterpret_cast<uint2*>(g_hs_h + i) = o;
}

__global__ __launch_bounds__(256) void convert_w_kernel(
    const int* __restrict__ dom, const float* __restrict__ Wh)
{
    const int b = blockIdx.y;
    const int idx = clamp_idx(dom[b]);
    for (int bb = 0; bb < b; bb++)
        if (clamp_idx(dom[bb]) == idx) return;

    const size_t i = ((size_t)blockIdx.x * 256 + threadIdx.x) * 8;
    const float* src = Wh + (size_t)idx * D_ * V_ + i;
    __half* dst = g_whB + (size_t)b * D_ * V_ + i;
    float4 v0 = *reinterpret_cast<const float4*>(src);
    float4 v1 = *reinterpret_cast<const float4*>(src + 4);
    uint4 o;
    o.x = pack_h2(v0.x, v0.y);
    o.y = pack_h2(v0.z, v0.w);
    o.z = pack_h2(v1.x, v1.y);
    o.w = pack_h2(v1.z, v1.w);
    *reinterpret_cast<uint4*>(dst) = o;
}

// ---------------- launch ----------------
extern "C" void kernel_launch(void* const* d_in, const int* in_sizes, int n_in,
                              void* d_out, int out_size)
{
    const float* hs      = (const float*)d_in[0];
    const int*   dom     = (const int*)  d_in[1];
    const float* W_base  = (const float*)d_in[2];
    const float* b_base  = (const float*)d_in[3];
    const float* W_heads = (const float*)d_in[4];
    const float* b_heads = (const float*)d_in[5];
    float* out = (float*)d_out;

    static bool attr_set = false;
    if (!attr_set) {
        cudaFuncSetAttribute(gemm_base_kernel,  cudaFuncAttributeMaxDynamicSharedMemorySize, SMEM_BASE_TOTAL);
        cudaFuncSetAttribute(gemm_heads_kernel, cudaFuncAttributeMaxDynamicSharedMemorySize, SMEM_HEADS_TOTAL);
        attr_set = true;
    }

    round_hs_kernel<<<(B_ * S_ * D_) / (256 * 4), 256>>>(hs);

    dim3 gC((D_ * V_) / (256 * 8), B_);           // (16000, 8)
    convert_w_kernel<<<gC, 256>>>(dom, W_heads);

    dim3 gA(D_ / BN, (B_ * S_) / BM, 1);          // (8, 16, 1)
    gemm_base_kernel<<<gA, 256, SMEM_BASE_TOTAL>>>(W_base, b_base);

    dim3 gB(S_ / BM, V_ / BN, B_);                // (2, 250, 8) m fastest
    gemm_heads_kernel<<<gB, 256, SMEM_HEADS_TOTAL>>>(dom, b_heads, out);
}